// round 1
// baseline (speedup 1.0000x reference)
#include <cuda_runtime.h>

// VanillaRNN: h[256,2048] recurrence, 511 steps, fp32.
// Each block owns NB=14 batch columns; thread i owns hidden row i.
// W_hh^T: 192 cols in smem (pad 257 -> conflict-free), 64 cols in registers.
// Packed fma.rn.f32x2 for 2x fp32 FMA throughput.

#define BATCH 2048
#define SEQ 512
#define TSTEPS 511           // reference iterates t in [0, T-1)
#define H 256
#define NB 14                // batch columns per block
#define NBP 16               // padded h row (floats) for vector LDS/STS
#define KS 192               // k-columns of W_hh^T kept in smem
#define KR 64                // k-columns of W_hh kept in registers (per-thread row slice)
#define WPAD 257             // smem row stride (floats) -> conflict-free transpose
#define NBLK ((BATCH + NB - 1) / NB)   // 147 blocks, one wave on 148 SMs
#define SMEM_FLOATS (KS * WPAD + H * NBP + 2 * NBP)
#define SMEM_BYTES (SMEM_FLOATS * 4)   // 213,888 B <= 227 KB opt-in

typedef unsigned long long u64;

__device__ __forceinline__ u64 pk2(float lo, float hi) {
    u64 r;
    asm("mov.b64 %0, {%1, %2};" : "=l"(r) : "f"(lo), "f"(hi));
    return r;
}
__device__ __forceinline__ void upk2(u64 v, float& lo, float& hi) {
    asm("mov.b64 {%0, %1}, %2;" : "=f"(lo), "=f"(hi) : "l"(v));
}
// d = a * b + d   (packed 2 x fp32)
__device__ __forceinline__ void fma2(u64& d, u64 a, u64 b) {
    asm("fma.rn.f32x2 %0, %1, %2, %0;" : "+l"(d) : "l"(a), "l"(b));
}

// tanh(x) = 1 - 2/(exp(2x)+1); __expf is MUFU.EX2-based, ~1e-6 rel err.
// Saturates correctly for |x| large (exp -> 0 or inf).
__device__ __forceinline__ float tanh_fast(float v) {
    float e = __expf(2.0f * v);
    return 1.0f - __fdividef(2.0f, e + 1.0f);
}

__global__ void __launch_bounds__(256, 1) VanillaRNN_54984171323420_kernel(
    const float* __restrict__ x,    // [2048, 512]
    const float* __restrict__ Whx,  // [256, 1]
    const float* __restrict__ Whh,  // [256, 256]
    const float* __restrict__ Wph,  // [10, 256]
    const float* __restrict__ bh,   // [256, 2048]
    const float* __restrict__ bp,   // [10, 2048]
    float* __restrict__ out)        // [2048, 10]
{
    extern __shared__ float sm[];
    float* Wt = sm;                    // [KS][WPAD] : Wt[k][i] = Whh[i][k]
    float* hs = sm + KS * WPAD;        // [H][NBP]   : h state (offset 197376 B, 16B aligned)
    float* xb = hs + H * NBP;          // [2][NBP]   : x double buffer

    const int tid = threadIdx.x;       // 0..255 ; also the hidden row this thread owns
    const int i = tid;
    const int j0 = blockIdx.x * NB;

    // ---- Load W_hh^T cols 0..KS-1 into smem ----
    // Read Whh[idx] coalesced (idx = i*256 + k); write Wt[k*257 + i]:
    // lanes step k -> addr stride 257 words -> banks rotate, conflict-free.
    for (int idx = tid; idx < H * H; idx += 256) {
        int kk = idx & (H - 1);
        int ii = idx >> 8;
        float v = Whh[idx];
        if (kk < KS) Wt[kk * WPAD + ii] = v;
    }

    // ---- Register slice: Whh[i][KS..255] (thread i only needs its own row) ----
    float Wr[KR];
#pragma unroll
    for (int r = 0; r < KR; r++) Wr[r] = Whh[i * H + KS + r];

    // ---- h0 = 0 ----
    for (int idx = tid; idx < H * NBP; idx += 256) hs[idx] = 0.0f;

    // ---- Per-thread constants: W_hx row, bias pairs ----
    const float whx = Whx[i];
    const u64 wpx = pk2(whx, whx);

    u64 bh2[NB / 2];
#pragma unroll
    for (int p = 0; p < NB / 2; p++) {
        int ja = j0 + 2 * p, jb = j0 + 2 * p + 1;
        float blo = (ja < BATCH) ? bh[i * BATCH + ja] : 0.0f;
        float bhi = (jb < BATCH) ? bh[i * BATCH + jb] : 0.0f;
        bh2[p] = pk2(blo, bhi);
    }

    // ---- x prefetch (double buffered in smem) ----
    const int jc = min(j0 + tid, BATCH - 1);
    if (tid < NB) xb[tid] = x[jc * SEQ + 0];
    __syncthreads();

    // ================= recurrence =================
    for (int t = 0; t < TSTEPS; t++) {
        const float* xc = xb + (t & 1) * NBP;
        float xnext = 0.0f;
        if (tid < NB) xnext = x[jc * SEQ + t + 1];   // t+1 <= 511 < SEQ, always in-bounds

        // acc = b_h + W_hx * x_t   (per batch column, packed pairs)
        u64 acc[NB / 2];
#pragma unroll
        for (int p = 0; p < NB / 2; p++) {
            u64 xp = *(const u64*)(xc + 2 * p);
            acc[p] = bh2[p];
            fma2(acc[p], wpx, xp);
        }

        // ---- smem-resident part of W_hh @ h ----
#pragma unroll 4
        for (int k = 0; k < KS; k++) {
            float w = Wt[k * WPAD + i];          // lanes i consecutive: conflict-free
            u64 wp = pk2(w, w);
            const float* hrow = hs + k * NBP;    // broadcast across warp
            ulonglong2 ha = *(const ulonglong2*)(hrow);        // j 0..3
            ulonglong2 hb = *(const ulonglong2*)(hrow + 4);    // j 4..7
            ulonglong2 hc = *(const ulonglong2*)(hrow + 8);    // j 8..11
            u64 hd = *(const u64*)(hrow + 12);                 // j 12..13
            fma2(acc[0], wp, ha.x); fma2(acc[1], wp, ha.y);
            fma2(acc[2], wp, hb.x); fma2(acc[3], wp, hb.y);
            fma2(acc[4], wp, hc.x); fma2(acc[5], wp, hc.y);
            fma2(acc[6], wp, hd);
        }

        // ---- register-resident part (k = KS..255) ----
#pragma unroll
        for (int r = 0; r < KR; r++) {
            u64 wp = pk2(Wr[r], Wr[r]);
            const float* hrow = hs + (KS + r) * NBP;
            ulonglong2 ha = *(const ulonglong2*)(hrow);
            ulonglong2 hb = *(const ulonglong2*)(hrow + 4);
            ulonglong2 hc = *(const ulonglong2*)(hrow + 8);
            u64 hd = *(const u64*)(hrow + 12);
            fma2(acc[0], wp, ha.x); fma2(acc[1], wp, ha.y);
            fma2(acc[2], wp, hb.x); fma2(acc[3], wp, hb.y);
            fma2(acc[4], wp, hc.x); fma2(acc[5], wp, hc.y);
            fma2(acc[6], wp, hd);
        }

        // ---- tanh + state update ----
        float hn[NB];
#pragma unroll
        for (int p = 0; p < NB / 2; p++) {
            float a, b;
            upk2(acc[p], a, b);
            hn[2 * p]     = tanh_fast(a);
            hn[2 * p + 1] = tanh_fast(b);
        }
        __syncthreads();   // all reads of hs(t) done
        float* hw = hs + i * NBP;
        *(float4*)(hw)      = make_float4(hn[0], hn[1], hn[2], hn[3]);
        *(float4*)(hw + 4)  = make_float4(hn[4], hn[5], hn[6], hn[7]);
        *(float4*)(hw + 8)  = make_float4(hn[8], hn[9], hn[10], hn[11]);
        *(float2*)(hw + 12) = make_float2(hn[12], hn[13]);
        if (tid < NB) xb[((t + 1) & 1) * NBP + tid] = xnext;
        __syncthreads();   // hs(t+1) visible
    }

    // ================= projection epilogue =================
    // out[j][c] = sum_k Wph[c][k] * h[k][j] + bp[c][j]
    for (int idx = tid; idx < 10 * H; idx += 256) Wt[idx] = Wph[idx];  // reuse Wt buffer
    __syncthreads();
    if (tid < 10 * NB) {
        int c = tid / NB;
        int jj = tid - c * NB;
        int j = j0 + jj;
        if (j < BATCH) {
            float s = bp[c * BATCH + j];
            const float* wr = Wt + c * H;
#pragma unroll 8
            for (int k = 0; k < H; k++) s = fmaf(wr[k], hs[k * NBP + jj], s);
            out[j * 10 + c] = s;
        }
    }
}

extern "C" void kernel_launch(void* const* d_in, const int* in_sizes, int n_in,
                              void* d_out, int out_size) {
    const float* x   = (const float*)d_in[0];
    const float* Whx = (const float*)d_in[1];
    const float* Whh = (const float*)d_in[2];
    const float* Wph = (const float*)d_in[3];
    const float* bh  = (const float*)d_in[4];
    const float* bp  = (const float*)d_in[5];
    float* out = (float*)d_out;

    cudaFuncSetAttribute(VanillaRNN_54984171323420_kernel,
                         cudaFuncAttributeMaxDynamicSharedMemorySize, SMEM_BYTES);
    VanillaRNN_54984171323420_kernel<<<NBLK, 256, SMEM_BYTES>>>(
        x, Whx, Whh, Wph, bh, bp, out);
}

// round 3
// speedup vs baseline: 3.2266x; 3.2266x over previous
#include <cuda_runtime.h>
#include <cuda_fp16.h>
#include <cstdint>

// VanillaRNN via warp-level HMMA (mma.sync.m16n8k16.f32.f16.f16.f32).
// Per CTA: D[256,16] = Whh @ h, 510 serial steps, fp16 3-pass hi/lo split.
// W_hi smem (128KB) ; W_lo: k<128 smem (64KB) + k>=128 register fragments.

#define BATCH 2048
#define SEQT  512
#define HDIM  256
#define NCOL  16
#define NBLK  128
#define NSTEPS 510        // + SIMT prologue = 511 h-updates (reference: t in [0,511))

// smem byte offsets
#define SM_WHI 0          // W_hi [256 rows][512B] fp16, chunk-XOR swizzle
#define SM_WLO 131072     // W_lo k<128 [256 rows][256B]
#define SM_BHI 196608     // h^T_hi [16 rows][512B]
#define SM_BLO 204800     // h^T_lo
#define SM_XR  212992     // x ring: 2 slots x 16 f32
#define SM_TOTAL 213504

__device__ __forceinline__ uint32_t s2u(const void* p) {
    uint32_t a;
    asm("{ .reg .u64 t; cvta.to.shared.u64 t, %1; cvt.u32.u64 %0, t; }" : "=r"(a) : "l"(p));
    return a;
}

#define LDSM4(r, a)                                                               \
    asm volatile("ldmatrix.sync.aligned.m8n8.x4.shared.b16 {%0,%1,%2,%3}, [%4];"  \
                 : "=r"((r)[0]), "=r"((r)[1]), "=r"((r)[2]), "=r"((r)[3])         \
                 : "r"(a))

__device__ __forceinline__ void mma16816(float* d, const uint32_t* a,
                                         uint32_t b0, uint32_t b1) {
    asm volatile("mma.sync.aligned.m16n8k16.row.col.f32.f16.f16.f32 "
                 "{%0,%1,%2,%3}, {%4,%5,%6,%7}, {%8,%9}, {%0,%1,%2,%3};"
                 : "+f"(d[0]), "+f"(d[1]), "+f"(d[2]), "+f"(d[3])
                 : "r"(a[0]), "r"(a[1]), "r"(a[2]), "r"(a[3]), "r"(b0), "r"(b1));
}

__device__ __forceinline__ float tanh_fast(float v) {
    float e = __expf(2.0f * v);
    return 1.0f - __fdividef(2.0f, e + 1.0f);
}

__device__ __forceinline__ uint32_t pkh(__half a, __half b) {
    return (uint32_t)__half_as_ushort(a) | ((uint32_t)__half_as_ushort(b) << 16);
}

__global__ void __launch_bounds__(256, 1) VanillaRNN_54984171323420_kernel(
    const float* __restrict__ x,    // [2048, 512]
    const float* __restrict__ Whx,  // [256, 1]
    const float* __restrict__ Whh,  // [256, 256]
    const float* __restrict__ Wph,  // [10, 256]
    const float* __restrict__ bh,   // [256, 2048]
    const float* __restrict__ bp,   // [10, 2048]
    float* __restrict__ out)        // [2048, 10]
{
    extern __shared__ char smc[];
    const uint32_t sb = s2u(smc);
    const int tid = threadIdx.x;
    const int w = tid >> 5;          // warp 0..7 -> m rows [32w, 32w+32)
    const int l = tid & 31;
    const int lq = l >> 2;           // 0..7 : row within 8x8 tile
    const int lr = (l & 3) * 2;      // 0,2,4,6 : col pair base
    const int lx = l >> 4;           // 0/1 : k-half for ldmatrix addressing
    const int l7 = l & 7;
    const int j0 = blockIdx.x * NCOL;

    // ---------------- W_hi / W_lo(k<128) into smem ----------------
    for (int idx = tid; idx < HDIM * HDIM; idx += 256) {
        int m = idx >> 8, k = idx & 255;
        float wv = Whh[idx];
        __half hi = __float2half_rn(wv);
        uint32_t ch = (uint32_t)(((k >> 3) ^ (m & 7)) << 4);
        *(__half*)(smc + SM_WHI + m * 512 + ch + (k & 7) * 2) = hi;
        if (k < 128) {
            __half lo = __float2half_rn(wv - __half2float(hi));
            *(__half*)(smc + SM_WLO + m * 256 + ch + (k & 7) * 2) = lo;
        }
    }

    // ---------------- W_lo register fragments for k in [128,256) ----------------
    // A-frag element order e: a0=(m,k) a1=(m+8,k) a2=(m,k+8) a3=(m+8,k+8)
    uint32_t alo[64];
#pragma unroll
    for (int ks = 0; ks < 8; ks++)
#pragma unroll
        for (int tm = 0; tm < 2; tm++)
#pragma unroll
            for (int e = 0; e < 4; e++) {
                int m = 32 * w + 16 * tm + lq + ((e & 1) ? 8 : 0);
                int k = 128 + 16 * ks + lr + ((e & 2) ? 8 : 0);
                float w0 = Whh[m * 256 + k], w1 = Whh[m * 256 + k + 1];
                __half h0 = __float2half_rn(w0), h1 = __float2half_rn(w1);
                __half l0 = __float2half_rn(w0 - __half2float(h0));
                __half l1 = __float2half_rn(w1 - __half2float(h1));
                alo[ks * 8 + tm * 4 + e] = pkh(l0, l1);
            }

    // ---------------- bias / Whx fragments (D layout: e&1->n+1, e>>1->m+8) ----------------
    float bias[16];
    float wx[2][2];
#pragma unroll
    for (int tm = 0; tm < 2; tm++) {
        wx[tm][0] = Whx[32 * w + 16 * tm + lq];
        wx[tm][1] = Whx[32 * w + 16 * tm + lq + 8];
#pragma unroll
        for (int tn = 0; tn < 2; tn++)
#pragma unroll
            for (int e = 0; e < 4; e++) {
                int m = 32 * w + 16 * tm + lq + ((e >> 1) ? 8 : 0);
                int n = 8 * tn + lr + (e & 1);
                bias[tm * 8 + tn * 4 + e] = bh[m * BATCH + j0 + n];
            }
    }

    // ---------------- x: slot1 <- x_0 ; preload x_1 ----------------
    float xn1 = 0.0f;
    if (tid < NCOL) {
        const float* xr = x + (j0 + tid) * SEQT;
        *(float*)(smc + SM_XR + 64 + tid * 4) = xr[0];
        xn1 = xr[1];
    }
    __syncthreads();

    // ---------------- prologue: h1 = tanh(b_h + Whx*x_0), h0 = 0 ----------------
    {
#pragma unroll
        for (int tm = 0; tm < 2; tm++)
#pragma unroll
            for (int tn = 0; tn < 2; tn++)
#pragma unroll
                for (int e = 0; e < 4; e++) {
                    int idx = tm * 8 + tn * 4 + e;
                    int n = 8 * tn + lr + (e & 1);
                    int mh = e >> 1;
                    float xv = *(const float*)(smc + SM_XR + 64 + n * 4);
                    float h = tanh_fast(bias[idx] + wx[tm][mh] * xv);
                    __half hi = __float2half_rn(h);
                    __half lo = __float2half_rn(h - __half2float(hi));
                    uint32_t Cm = (uint32_t)(4 * w + 2 * tm + mh);
                    uint32_t off = (uint32_t)n * 512 + ((Cm ^ (n & 7)) << 4) + lq * 2;
                    *(__half*)(smc + SM_BHI + off) = hi;
                    *(__half*)(smc + SM_BLO + off) = lo;
                }
        if (tid < NCOL) *(float*)(smc + SM_XR + tid * 4) = xn1;  // slot0 <- x_1
    }

    // per-thread ldmatrix row bases (invariant)
    const uint32_t rowA0  = sb + SM_WHI + (uint32_t)(32 * w + (l & 15)) * 512;
    const uint32_t rowA1  = rowA0 + 16 * 512;
    const uint32_t rowAL0 = sb + SM_WLO + (uint32_t)(32 * w + (l & 15)) * 256;
    const uint32_t rowAL1 = rowAL0 + 16 * 256;
    const uint32_t rowB   = sb + SM_BHI + (uint32_t)(l & 15) * 512;

    // ================= recurrence: 510 HMMA steps =================
#pragma unroll 1
    for (int it = 0; it < NSTEPS; it++) {
        // prefetch x_{it+2} (it+2 <= 511, always in-bounds)
        float xnext = 0.0f;
        if (tid < NCOL) xnext = x[(j0 + tid) * SEQT + it + 2];

        __syncthreads();   // (A) h_{it+1} stores visible

        float d[16];
#pragma unroll
        for (int q = 0; q < 16; q++) d[q] = 0.0f;

        // ---- ksteps 0..7 : A_lo from smem ----
#pragma unroll
        for (int ks = 0; ks < 8; ks++) {
            const uint32_t ch = (uint32_t)(((2 * ks + lx) ^ l7) << 4);
            uint32_t ah0[4], ah1[4], bh4[4], bl4[4], al0[4], al1[4];
            LDSM4(ah0, rowA0 + ch);
            LDSM4(ah1, rowA1 + ch);
            LDSM4(bh4, rowB + ch);
            LDSM4(bl4, rowB + 8192 + ch);
            LDSM4(al0, rowAL0 + ch);
            LDSM4(al1, rowAL1 + ch);
            mma16816(&d[0],  ah0, bh4[0], bh4[2]);
            mma16816(&d[0],  al0, bh4[0], bh4[2]);
            mma16816(&d[0],  ah0, bl4[0], bl4[2]);
            mma16816(&d[4],  ah0, bh4[1], bh4[3]);
            mma16816(&d[4],  al0, bh4[1], bh4[3]);
            mma16816(&d[4],  ah0, bl4[1], bl4[3]);
            mma16816(&d[8],  ah1, bh4[0], bh4[2]);
            mma16816(&d[8],  al1, bh4[0], bh4[2]);
            mma16816(&d[8],  ah1, bl4[0], bl4[2]);
            mma16816(&d[12], ah1, bh4[1], bh4[3]);
            mma16816(&d[12], al1, bh4[1], bh4[3]);
            mma16816(&d[12], ah1, bl4[1], bl4[3]);
        }
        // ---- ksteps 8..15 : A_lo from registers ----
#pragma unroll
        for (int k2 = 0; k2 < 8; k2++) {
            const uint32_t ch = (uint32_t)(((16 + 2 * k2 + lx) ^ l7) << 4);
            uint32_t ah0[4], ah1[4], bh4[4], bl4[4];
            LDSM4(ah0, rowA0 + ch);
            LDSM4(ah1, rowA1 + ch);
            LDSM4(bh4, rowB + ch);
            LDSM4(bl4, rowB + 8192 + ch);
            const uint32_t* al0 = &alo[k2 * 8];
            const uint32_t* al1 = &alo[k2 * 8 + 4];
            mma16816(&d[0],  ah0, bh4[0], bh4[2]);
            mma16816(&d[0],  al0, bh4[0], bh4[2]);
            mma16816(&d[0],  ah0, bl4[0], bl4[2]);
            mma16816(&d[4],  ah0, bh4[1], bh4[3]);
            mma16816(&d[4],  al0, bh4[1], bh4[3]);
            mma16816(&d[4],  ah0, bl4[1], bl4[3]);
            mma16816(&d[8],  ah1, bh4[0], bh4[2]);
            mma16816(&d[8],  al1, bh4[0], bh4[2]);
            mma16816(&d[8],  ah1, bl4[0], bl4[2]);
            mma16816(&d[12], ah1, bh4[1], bh4[3]);
            mma16816(&d[12], al1, bh4[1], bh4[3]);
            mma16816(&d[12], ah1, bl4[1], bl4[3]);
        }

        __syncthreads();   // (B) all reads of h_{it+1} done

        // ---- epilogue: h_{it+2} = tanh(D + b_h + Whx*x_{it+1}) ----
        const uint32_t xsl = (uint32_t)(SM_XR + (it & 1) * 64);
#pragma unroll
        for (int tm = 0; tm < 2; tm++)
#pragma unroll
            for (int tn = 0; tn < 2; tn++)
#pragma unroll
                for (int e = 0; e < 4; e++) {
                    int idx = tm * 8 + tn * 4 + e;
                    int n = 8 * tn + lr + (e & 1);
                    int mh = e >> 1;
                    float xv = *(const float*)(smc + xsl + n * 4);
                    float pre = d[idx] + bias[idx] + wx[tm][mh] * xv;
                    float h = tanh_fast(pre);
                    __half hi = __float2half_rn(h);
                    __half lo = __float2half_rn(h - __half2float(hi));
                    uint32_t Cm = (uint32_t)(4 * w + 2 * tm + mh);
                    uint32_t off = (uint32_t)n * 512 + ((Cm ^ (n & 7)) << 4) + lq * 2;
                    *(__half*)(smc + SM_BHI + off) = hi;
                    *(__half*)(smc + SM_BLO + off) = lo;
                }
        if (tid < NCOL) *(float*)(smc + SM_XR + ((it + 1) & 1) * 64 + tid * 4) = xnext;
    }

    __syncthreads();

    // ================= projection: out = Wph @ h + bp =================
    if (tid < 10 * NCOL) {
        const int c = tid >> 4, j = tid & 15;
        float s = bp[c * BATCH + j0 + j];
        const float* wr = Wph + c * HDIM;
#pragma unroll 8
        for (int k = 0; k < HDIM; k++) {
            uint32_t off = (uint32_t)j * 512 + ((((uint32_t)k >> 3) ^ (j & 7)) << 4) + (k & 7) * 2;
            float hv = __half2float(*(__half*)(smc + SM_BHI + off)) +
                       __half2float(*(__half*)(smc + SM_BLO + off));
            s = fmaf(wr[k], hv, s);
        }
        out[(j0 + j) * 10 + c] = s;
    }
}

extern "C" void kernel_launch(void* const* d_in, const int* in_sizes, int n_in,
                              void* d_out, int out_size) {
    const float* x   = (const float*)d_in[0];
    const float* Whx = (const float*)d_in[1];
    const float* Whh = (const float*)d_in[2];
    const float* Wph = (const float*)d_in[3];
    const float* bh  = (const float*)d_in[4];
    const float* bp  = (const float*)d_in[5];
    float* out = (float*)d_out;

    cudaFuncSetAttribute(VanillaRNN_54984171323420_kernel,
                         cudaFuncAttributeMaxDynamicSharedMemorySize, SM_TOTAL);
    VanillaRNN_54984171323420_kernel<<<NBLK, 256, SM_TOTAL>>>(
        x, Whx, Whh, Wph, bh, bp, out);
}

// round 4
// speedup vs baseline: 3.4042x; 1.0550x over previous
#include <cuda_runtime.h>
#include <cuda_fp16.h>
#include <cstdint>

// VanillaRNN via warp-level HMMA (mma.sync.m16n8k16.f32.f16.f16.f32).
// Per CTA: D[256,16] = Whh @ h, 510 serial steps, fp16 3-pass hi/lo split.
// R4: double-buffered h -> single __syncthreads per step; bias preloaded
// into accumulators; x prefetch hoisted.

#define BATCH 2048
#define SEQT  512
#define HDIM  256
#define NCOL  16
#define NBLK  128
#define NSTEPS 510        // + SIMT prologue = 511 h-updates

// smem byte offsets
#define SM_WHI 0          // W_hi [256 rows][512B] fp16, chunk-XOR swizzle
#define SM_WLO 131072     // W_lo k<128 [256 rows][256B]
#define SM_B   196608     // h buffers: [buf0: hi 8K | lo 8K][buf1: hi 8K | lo 8K]
#define SM_XR  229376     // x ring: 2 slots x 16 f32
#define SM_TOTAL 229504   // < 232448 (227KB)

__device__ __forceinline__ uint32_t s2u(const void* p) {
    uint32_t a;
    asm("{ .reg .u64 t; cvta.to.shared.u64 t, %1; cvt.u32.u64 %0, t; }" : "=r"(a) : "l"(p));
    return a;
}

#define LDSM4(r, a)                                                               \
    asm volatile("ldmatrix.sync.aligned.m8n8.x4.shared.b16 {%0,%1,%2,%3}, [%4];"  \
                 : "=r"((r)[0]), "=r"((r)[1]), "=r"((r)[2]), "=r"((r)[3])         \
                 : "r"(a))

__device__ __forceinline__ void mma16816(float* d, const uint32_t* a,
                                         uint32_t b0, uint32_t b1) {
    asm volatile("mma.sync.aligned.m16n8k16.row.col.f32.f16.f16.f32 "
                 "{%0,%1,%2,%3}, {%4,%5,%6,%7}, {%8,%9}, {%0,%1,%2,%3};"
                 : "+f"(d[0]), "+f"(d[1]), "+f"(d[2]), "+f"(d[3])
                 : "r"(a[0]), "r"(a[1]), "r"(a[2]), "r"(a[3]), "r"(b0), "r"(b1));
}

__device__ __forceinline__ float tanh_fast(float v) {
    float e = __expf(2.0f * v);
    return 1.0f - __fdividef(2.0f, e + 1.0f);
}

__device__ __forceinline__ uint32_t pkh(__half a, __half b) {
    return (uint32_t)__half_as_ushort(a) | ((uint32_t)__half_as_ushort(b) << 16);
}

__global__ void __launch_bounds__(256, 1) VanillaRNN_54984171323420_kernel(
    const float* __restrict__ x,    // [2048, 512]
    const float* __restrict__ Whx,  // [256, 1]
    const float* __restrict__ Whh,  // [256, 256]
    const float* __restrict__ Wph,  // [10, 256]
    const float* __restrict__ bh,   // [256, 2048]
    const float* __restrict__ bp,   // [10, 2048]
    float* __restrict__ out)        // [2048, 10]
{
    extern __shared__ char smc[];
    const uint32_t sb = s2u(smc);
    const int tid = threadIdx.x;
    const int w = tid >> 5;          // warp 0..7 -> m rows [32w, 32w+32)
    const int l = tid & 31;
    const int lq = l >> 2;
    const int lr = (l & 3) * 2;
    const int lx = l >> 4;
    const int l7 = l & 7;
    const int j0 = blockIdx.x * NCOL;

    // ---------------- W_hi / W_lo(k<128) into smem ----------------
    for (int idx = tid; idx < HDIM * HDIM; idx += 256) {
        int m = idx >> 8, k = idx & 255;
        float wv = Whh[idx];
        __half hi = __float2half_rn(wv);
        uint32_t ch = (uint32_t)(((k >> 3) ^ (m & 7)) << 4);
        *(__half*)(smc + SM_WHI + m * 512 + ch + (k & 7) * 2) = hi;
        if (k < 128) {
            __half lo = __float2half_rn(wv - __half2float(hi));
            *(__half*)(smc + SM_WLO + m * 256 + ch + (k & 7) * 2) = lo;
        }
    }

    // ---------------- W_lo register fragments for k in [128,256) ----------------
    uint32_t alo[64];
#pragma unroll
    for (int ks = 0; ks < 8; ks++)
#pragma unroll
        for (int tm = 0; tm < 2; tm++)
#pragma unroll
            for (int e = 0; e < 4; e++) {
                int m = 32 * w + 16 * tm + lq + ((e & 1) ? 8 : 0);
                int k = 128 + 16 * ks + lr + ((e & 2) ? 8 : 0);
                float w0 = Whh[m * 256 + k], w1 = Whh[m * 256 + k + 1];
                __half h0 = __float2half_rn(w0), h1 = __float2half_rn(w1);
                __half l0 = __float2half_rn(w0 - __half2float(h0));
                __half l1 = __float2half_rn(w1 - __half2float(h1));
                alo[ks * 8 + tm * 4 + e] = pkh(l0, l1);
            }

    // ---------------- bias / Whx fragments ----------------
    float bias[16];
    float wx[2][2];
#pragma unroll
    for (int tm = 0; tm < 2; tm++) {
        wx[tm][0] = Whx[32 * w + 16 * tm + lq];
        wx[tm][1] = Whx[32 * w + 16 * tm + lq + 8];
#pragma unroll
        for (int tn = 0; tn < 2; tn++)
#pragma unroll
            for (int e = 0; e < 4; e++) {
                int m = 32 * w + 16 * tm + lq + ((e >> 1) ? 8 : 0);
                int n = 8 * tn + lr + (e & 1);
                bias[tm * 8 + tn * 4 + e] = bh[m * BATCH + j0 + n];
            }
    }

    // ---------------- x: slot1 <- x_0 ; preload x_1 ----------------
    float xn1 = 0.0f;
    if (tid < NCOL) {
        const float* xr = x + (j0 + tid) * SEQT;
        *(float*)(smc + SM_XR + 64 + tid * 4) = xr[0];
        xn1 = xr[1];
    }
    __syncthreads();

    // ---------------- prologue: h1 = tanh(b_h + Whx*x_0) -> buf0 ----------------
    {
#pragma unroll
        for (int tm = 0; tm < 2; tm++)
#pragma unroll
            for (int tn = 0; tn < 2; tn++)
#pragma unroll
                for (int e = 0; e < 4; e++) {
                    int idx = tm * 8 + tn * 4 + e;
                    int n = 8 * tn + lr + (e & 1);
                    int mh = e >> 1;
                    float xv = *(const float*)(smc + SM_XR + 64 + n * 4);
                    float h = tanh_fast(bias[idx] + wx[tm][mh] * xv);
                    __half hi = __float2half_rn(h);
                    __half lo = __float2half_rn(h - __half2float(hi));
                    uint32_t Cm = (uint32_t)(4 * w + 2 * tm + mh);
                    uint32_t off = (uint32_t)n * 512 + ((Cm ^ (n & 7)) << 4) + lq * 2;
                    *(__half*)(smc + SM_B + off) = hi;
                    *(__half*)(smc + SM_B + 8192 + off) = lo;
                }
        if (tid < NCOL) *(float*)(smc + SM_XR + tid * 4) = xn1;  // slot0 <- x_1
    }
    __syncthreads();

    // per-thread invariant bases
    const uint32_t rowA0  = sb + SM_WHI + (uint32_t)(32 * w + (l & 15)) * 512;
    const uint32_t rowA1  = rowA0 + 16 * 512;
    const uint32_t rowAL0 = sb + SM_WLO + (uint32_t)(32 * w + (l & 15)) * 256;
    const uint32_t rowAL1 = rowAL0 + 16 * 256;
    const uint32_t rowBb  = sb + SM_B + (uint32_t)(l & 15) * 512;

    // ================= recurrence: 510 HMMA steps, 1 bar/step =================
#pragma unroll 2
    for (int it = 0; it < NSTEPS; it++) {
        const int p = it & 1;                 // read buf p, write buf 1-p
        // prefetch x_{it+2}
        float xnext = 0.0f;
        if (tid < NCOL) xnext = x[(j0 + tid) * SEQT + it + 2];

        const uint32_t rowB = rowBb + (uint32_t)p * 16384;

        float d[16];
#pragma unroll
        for (int q = 0; q < 16; q++) d[q] = bias[q];

        // ---- ksteps 0..7 : A_lo from smem ----
#pragma unroll
        for (int ks = 0; ks < 8; ks++) {
            const uint32_t ch = (uint32_t)(((2 * ks + lx) ^ l7) << 4);
            uint32_t ah0[4], ah1[4], bh4[4], bl4[4], al0[4], al1[4];
            LDSM4(bh4, rowB + ch);
            LDSM4(ah0, rowA0 + ch);
            LDSM4(bl4, rowB + 8192 + ch);
            LDSM4(ah1, rowA1 + ch);
            LDSM4(al0, rowAL0 + ch);
            LDSM4(al1, rowAL1 + ch);
            mma16816(&d[0],  ah0, bh4[0], bh4[2]);
            mma16816(&d[0],  al0, bh4[0], bh4[2]);
            mma16816(&d[0],  ah0, bl4[0], bl4[2]);
            mma16816(&d[4],  ah0, bh4[1], bh4[3]);
            mma16816(&d[4],  al0, bh4[1], bh4[3]);
            mma16816(&d[4],  ah0, bl4[1], bl4[3]);
            mma16816(&d[8],  ah1, bh4[0], bh4[2]);
            mma16816(&d[8],  al1, bh4[0], bh4[2]);
            mma16816(&d[8],  ah1, bl4[0], bl4[2]);
            mma16816(&d[12], ah1, bh4[1], bh4[3]);
            mma16816(&d[12], al1, bh4[1], bh4[3]);
            mma16816(&d[12], ah1, bl4[1], bl4[3]);
        }
        // ---- ksteps 8..15 : A_lo from registers ----
#pragma unroll
        for (int k2 = 0; k2 < 8; k2++) {
            const uint32_t ch = (uint32_t)(((16 + 2 * k2 + lx) ^ l7) << 4);
            uint32_t ah0[4], ah1[4], bh4[4], bl4[4];
            LDSM4(bh4, rowB + ch);
            LDSM4(ah0, rowA0 + ch);
            LDSM4(bl4, rowB + 8192 + ch);
            LDSM4(ah1, rowA1 + ch);
            const uint32_t* al0 = &alo[k2 * 8];
            const uint32_t* al1 = &alo[k2 * 8 + 4];
            mma16816(&d[0],  ah0, bh4[0], bh4[2]);
            mma16816(&d[0],  al0, bh4[0], bh4[2]);
            mma16816(&d[0],  ah0, bl4[0], bl4[2]);
            mma16816(&d[4],  ah0, bh4[1], bh4[3]);
            mma16816(&d[4],  al0, bh4[1], bh4[3]);
            mma16816(&d[4],  ah0, bl4[1], bl4[3]);
            mma16816(&d[8],  ah1, bh4[0], bh4[2]);
            mma16816(&d[8],  al1, bh4[0], bh4[2]);
            mma16816(&d[8],  ah1, bl4[0], bl4[2]);
            mma16816(&d[12], ah1, bh4[1], bh4[3]);
            mma16816(&d[12], al1, bh4[1], bh4[3]);
            mma16816(&d[12], ah1, bl4[1], bl4[3]);
        }

        // ---- epilogue: h_{it+2} = tanh(D + Whx*x_{it+1}) -> buf 1-p ----
        const uint32_t xsl = (uint32_t)(SM_XR + p * 64);
        const uint32_t bufw = (uint32_t)(SM_B + (1 - p) * 16384);
#pragma unroll
        for (int tm = 0; tm < 2; tm++)
#pragma unroll
            for (int tn = 0; tn < 2; tn++)
#pragma unroll
                for (int e = 0; e < 4; e++) {
                    int idx = tm * 8 + tn * 4 + e;
                    int n = 8 * tn + lr + (e & 1);
                    int mh = e >> 1;
                    float xv = *(const float*)(smc + xsl + n * 4);
                    float pre = fmaf(wx[tm][mh], xv, d[idx]);
                    float h = tanh_fast(pre);
                    __half hi = __float2half_rn(h);
                    __half lo = __float2half_rn(h - __half2float(hi));
                    uint32_t Cm = (uint32_t)(4 * w + 2 * tm + mh);
                    uint32_t off = (uint32_t)n * 512 + ((Cm ^ (n & 7)) << 4) + lq * 2;
                    *(__half*)(smc + bufw + off) = hi;
                    *(__half*)(smc + bufw + 8192 + off) = lo;
                }
        if (tid < NCOL) *(float*)(smc + SM_XR + (1 - p) * 64 + tid * 4) = xnext;
        __syncthreads();
    }

    // ================= projection: out = Wph @ h + bp =================
    // final h (after 511 updates) lives in buf0 (it=509 wrote 1-p=0)
    if (tid < 10 * NCOL) {
        const int c = tid >> 4, j = tid & 15;
        float s = bp[c * BATCH + j0 + j];
        const float* wr = Wph + c * HDIM;
#pragma unroll 8
        for (int k = 0; k < HDIM; k++) {
            uint32_t off = (uint32_t)j * 512 + ((((uint32_t)k >> 3) ^ (j & 7)) << 4) + (k & 7) * 2;
            float hv = __half2float(*(__half*)(smc + SM_B + off)) +
                       __half2float(*(__half*)(smc + SM_B + 8192 + off));
            s = fmaf(wr[k], hv, s);
        }
        out[(j0 + j) * 10 + c] = s;
    }
}

extern "C" void kernel_launch(void* const* d_in, const int* in_sizes, int n_in,
                              void* d_out, int out_size) {
    const float* x   = (const float*)d_in[0];
    const float* Whx = (const float*)d_in[1];
    const float* Whh = (const float*)d_in[2];
    const float* Wph = (const float*)d_in[3];
    const float* bh  = (const float*)d_in[4];
    const float* bp  = (const float*)d_in[5];
    float* out = (float*)d_out;

    cudaFuncSetAttribute(VanillaRNN_54984171323420_kernel,
                         cudaFuncAttributeMaxDynamicSharedMemorySize, SM_TOTAL);
    VanillaRNN_54984171323420_kernel<<<NBLK, 256, SM_TOTAL>>>(
        x, Whx, Whh, Wph, bh, bp, out);
}